// round 13
// baseline (speedup 1.0000x reference)
#include <cuda_runtime.h>
#include <cuda_bf16.h>
#include <math_constants.h>
#include <cstdint>

#define NN 25600
#define EE 409600
#define GB 8
#define FF 7
#define HH 300
#define LL 100

// ---- gemm_out smem layout (unchanged from R11) ----
#define SOFF_AH   0
#define SOFF_AL   16384
#define SOFF_BH   32768
#define SOFF_BL   49152
#define SMEMTC    66064

// ---- gemm_mid smem layout (N=160 tile) ----
#define M_AH   0        // A hi  [128 rows][64 k] bf16, 128B rows, SW128
#define M_AL   16384    // A lo
#define M_BH   32768    // B hi  [160 n-rows][64 k]
#define M_BL   53248    // B lo
#define M_SRC  73728    // int[128]
#define SMEM_MID 81920  // stage overlay: u32 [128][160]

// ---------------- scratch (static device globals; no runtime allocation) ----
__device__ float    g_P[NN * HH];
__device__ float    g_Q[NN * HH];
__device__ uint32_t g_h2hl[(size_t)EE * HH];       // packed (hi|lo<<16) bf16 pair
__device__ float    g_node[NN * LL];
__device__ float    g_pooled[GB * 3 * LL];
// pre-split / transposed / padded weights: B[n][k] = W[k][n]
__device__ __nv_bfloat16 g_W2h[2][2 * 160 * 320];  // [layer][slab*160 rows][320]
__device__ __nv_bfloat16 g_W2l[2][2 * 160 * 320];
__device__ __nv_bfloat16 g_W3h[2][128 * 320];
__device__ __nv_bfloat16 g_W3l[2][128 * 320];

// ---------------- PTX helpers (baseline compute_103 instructions only) ------
__device__ __forceinline__ uint32_t smem_u32(const void* p) {
    uint32_t a;
    asm("{ .reg .u64 t; cvta.to.shared.u64 t, %1; cvt.u32.u64 %0, t; }"
        : "=r"(a) : "l"(p));
    return a;
}
__device__ __forceinline__ uint32_t sw128(uint32_t o) {
    return o ^ ((o >> 3) & 0x70);
}
__device__ __forceinline__ uint32_t bf2pack(float hi, float lo) {
    uint32_t r;
    asm("cvt.rn.bf16x2.f32 %0, %1, %2;" : "=r"(r) : "f"(hi), "f"(lo));
    return r;
}
__device__ __forceinline__ void ldsm4(uint32_t addr, uint32_t* r) {
    asm volatile("ldmatrix.sync.aligned.m8n8.x4.shared.b16 {%0,%1,%2,%3}, [%4];"
                 : "=r"(r[0]), "=r"(r[1]), "=r"(r[2]), "=r"(r[3]) : "r"(addr));
}
__device__ __forceinline__ void mma16816(float* d, const uint32_t* a,
                                         uint32_t b0, uint32_t b1) {
    asm volatile(
        "mma.sync.aligned.m16n8k16.row.col.f32.bf16.bf16.f32 "
        "{%0,%1,%2,%3}, {%4,%5,%6,%7}, {%8,%9}, {%0,%1,%2,%3};"
        : "+f"(d[0]), "+f"(d[1]), "+f"(d[2]), "+f"(d[3])
        : "r"(a[0]), "r"(a[1]), "r"(a[2]), "r"(a[3]), "r"(b0), "r"(b1));
}

// ---------------------------------------------------------------------------
// split weights into bf16 hi/lo planes, transposed to B[n][k], padded.
// grid = n_slabs * rows_per_slab blocks; slab s covers cols [s*valid, s*valid+valid).
__global__ void split_w(const float* __restrict__ W,
                        __nv_bfloat16* __restrict__ oh,
                        __nv_bfloat16* __restrict__ ol,
                        int K, int Ncols, int rows_per_slab, int valid) {
    int b = blockIdx.x;
    int slab = b / rows_per_slab;
    int n_local = b - slab * rows_per_slab;
    int k = threadIdx.x;
    int n = slab * valid + n_local;
    float v = 0.f;
    if (n_local < valid && k < K && n < Ncols) v = W[k * Ncols + n];
    __nv_bfloat16 h = __float2bfloat16(v);
    __nv_bfloat16 l = __float2bfloat16(v - __bfloat162float(h));
    oh[b * 320 + k] = h;
    ol[b * 320 + k] = l;
}

// ---------------------------------------------------------------------------
// front: per-node first MLP layer, exploiting linearity of concat([x_i, x_j-x_i]).
__global__ void front_kernel(const float* __restrict__ xin, int K,
                             const float* __restrict__ W,
                             const float* __restrict__ b,
                             int from_node) {
    __shared__ float xs[16 * 100];
    const float* __restrict__ x = from_node ? g_node : xin;
    int n0 = blockIdx.x * 16;
    int j = threadIdx.x;
    for (int i = threadIdx.x; i < 16 * K; i += 300)
        xs[i] = x[n0 * K + i];
    __syncthreads();

    float accP[16], accQ[16];
    float bj = b[j];
#pragma unroll
    for (int r = 0; r < 16; r++) { accP[r] = bj; accQ[r] = 0.f; }
    for (int k = 0; k < K; k++) {
        float wa = W[k * HH + j];
        float wb = W[(K + k) * HH + j];
        float d = wa - wb;
#pragma unroll
        for (int r = 0; r < 16; r++) {
            float xv = xs[r * K + k];
            accP[r] = fmaf(xv, d, accP[r]);
            accQ[r] = fmaf(xv, wb, accQ[r]);
        }
    }
#pragma unroll
    for (int r = 0; r < 16; r++) {
        g_P[(n0 + r) * HH + j] = accP[r];
        g_Q[(n0 + r) * HH + j] = accQ[r];
    }
}

// ---------------------------------------------------------------------------
// gemm_mid_mma: h2[128 edges, 150-col slab] = relu(relu(P+Q) @ W2 + b2).
// N tile = 160 (150 valid). 8 warps = 4M x 2N, warp tile 32x80.
__global__ __launch_bounds__(256, 2)
void gemm_mid_mma(const int* __restrict__ src,
                  const __nv_bfloat16* __restrict__ Bh_g,
                  const __nv_bfloat16* __restrict__ Bl_g,
                  const float* __restrict__ bias) {
    extern __shared__ char smem[];
    uint32_t sb = smem_u32(smem);
    int tid = threadIdx.x, wid = tid >> 5, lane = tid & 31;
    int mw = wid & 3, nw = wid >> 2;
    int slab = blockIdx.x;
    int row0 = blockIdx.y * 128;
    int n0 = blockIdx.y * 8;
    int* s_src = (int*)(smem + M_SRC);

    if (tid < 128) s_src[tid] = src[row0 + tid];
    __syncthreads();

    const __nv_bfloat16* bhp = Bh_g + slab * (160 * 320);
    const __nv_bfloat16* blp = Bl_g + slab * (160 * 320);

    float acc[2][10][4];
#pragma unroll
    for (int mt = 0; mt < 2; mt++)
#pragma unroll
        for (int nt = 0; nt < 10; nt++)
#pragma unroll
            for (int e = 0; e < 4; e++) acc[mt][nt][e] = 0.f;

    int arow = mw * 32 + (lane & 15);
    int akb = (lane >> 4) * 16;
    int bn = nw * 80 + (lane & 7) + ((lane >> 4) << 3);
    int bkb = ((lane >> 3) & 1) * 16;

    for (int ch = 0; ch < 5; ch++) {
        int k0 = ch * 64;
        // A tile: gather relu(P+Q), split hi/lo, swizzled STS
        for (int i = tid; i < 2048; i += 256) {
            int row = i >> 4, kq = i & 15;
            int kg = k0 + kq * 4;
            float4 v = make_float4(0.f, 0.f, 0.f, 0.f);
            if (kg < 300) {
                float4 p = *(const float4*)&g_P[(n0 + (row >> 4)) * HH + kg];
                float4 q = *(const float4*)&g_Q[s_src[row] * HH + kg];
                v.x = fmaxf(p.x + q.x, 0.f);
                v.y = fmaxf(p.y + q.y, 0.f);
                v.z = fmaxf(p.z + q.z, 0.f);
                v.w = fmaxf(p.w + q.w, 0.f);
            }
            uint32_t h01 = bf2pack(v.y, v.x);
            uint32_t h23 = bf2pack(v.w, v.z);
            float l0 = v.x - __uint_as_float(h01 << 16);
            float l1 = v.y - __uint_as_float(h01 & 0xFFFF0000u);
            float l2 = v.z - __uint_as_float(h23 << 16);
            float l3 = v.w - __uint_as_float(h23 & 0xFFFF0000u);
            uint32_t q01 = bf2pack(l1, l0);
            uint32_t q23 = bf2pack(l3, l2);
            uint32_t o = sw128((uint32_t)(row * 128 + kq * 8));
            *(uint2*)(smem + M_AH + o) = make_uint2(h01, h23);
            *(uint2*)(smem + M_AL + o) = make_uint2(q01, q23);
        }
        // B tiles (both planes): 160 rows x 16 uint2 each
        for (int i = tid; i < 5120; i += 256) {
            int pl = i >= 2560;
            int j = pl ? i - 2560 : i;
            int n = j >> 4, kq = j & 15;
            uint2 w = *(const uint2*)((pl ? blp : bhp) + n * 320 + k0 + kq * 4);
            uint32_t o = sw128((uint32_t)(n * 128 + kq * 8));
            *(uint2*)(smem + (pl ? M_BL : M_BH) + o) = w;
        }
        __syncthreads();
        // compute
#pragma unroll
        for (int s = 0; s < 4; s++) {
            uint32_t ah[2][4], al[2][4];
#pragma unroll
            for (int mt = 0; mt < 2; mt++) {
                uint32_t off = sw128((uint32_t)((arow + mt * 16) * 128 + akb + s * 32));
                ldsm4(sb + M_AH + off, ah[mt]);
                ldsm4(sb + M_AL + off, al[mt]);
            }
#pragma unroll
            for (int p = 0; p < 5; p++) {
                uint32_t bb[4];
                uint32_t off = sw128((uint32_t)((bn + p * 16) * 128 + bkb + s * 32));
                ldsm4(sb + M_BH + off, bb);
#pragma unroll
                for (int mt = 0; mt < 2; mt++) {
                    mma16816(acc[mt][2 * p + 0], ah[mt], bb[0], bb[1]);
                    mma16816(acc[mt][2 * p + 1], ah[mt], bb[2], bb[3]);
                    mma16816(acc[mt][2 * p + 0], al[mt], bb[0], bb[1]);
                    mma16816(acc[mt][2 * p + 1], al[mt], bb[2], bb[3]);
                }
            }
#pragma unroll
            for (int p = 0; p < 5; p++) {
                uint32_t bb[4];
                uint32_t off = sw128((uint32_t)((bn + p * 16) * 128 + bkb + s * 32));
                ldsm4(sb + M_BL + off, bb);
#pragma unroll
                for (int mt = 0; mt < 2; mt++) {
                    mma16816(acc[mt][2 * p + 0], ah[mt], bb[0], bb[1]);
                    mma16816(acc[mt][2 * p + 1], ah[mt], bb[2], bb[3]);
                }
            }
        }
        __syncthreads();
    }

    // epilogue: bias + relu + bf16 hi/lo pack -> stage -> global
    uint32_t* stage = (uint32_t*)smem;   // [128][160] u32 overlays tiles
#pragma unroll
    for (int mt = 0; mt < 2; mt++)
#pragma unroll
        for (int nt = 0; nt < 10; nt++) {
            int c = nw * 80 + nt * 8 + (lane & 3) * 2;
            int r0 = mw * 32 + mt * 16 + (lane >> 2);
#pragma unroll
            for (int e = 0; e < 4; e++) {
                int cc = c + (e & 1);
                int rr = (e < 2) ? r0 : r0 + 8;
                if (cc < 150) {
                    float v = fmaxf(acc[mt][nt][e] + bias[slab * 150 + cc], 0.f);
                    __nv_bfloat16 hh = __float2bfloat16(v);
                    __nv_bfloat16 ll = __float2bfloat16(v - __bfloat162float(hh));
                    stage[rr * 160 + cc] =
                        ((uint32_t)__bfloat16_as_ushort(ll) << 16) |
                        __bfloat16_as_ushort(hh);
                }
            }
        }
    __syncthreads();
    for (int i = tid; i < 19200; i += 256) {
        int row = i / 150, c = i - row * 150;
        g_h2hl[(size_t)(row0 + row) * HH + slab * 150 + c] = stage[row * 160 + c];
    }
}

// ---------------------------------------------------------------------------
// gemm_out_mma: h3 = h2 @ W3 (bf16 split), fused max over 16-edge groups,
// +b3, relu -> g_node. (unchanged from R11)
__global__ __launch_bounds__(256, 2)
void gemm_out_mma(const __nv_bfloat16* __restrict__ Bh_g,
                  const __nv_bfloat16* __restrict__ Bl_g,
                  const float* __restrict__ bias) {
    extern __shared__ char smem[];
    uint32_t sb = smem_u32(smem);
    int tid = threadIdx.x, wid = tid >> 5, lane = tid & 31;
    int mw = wid & 3, nw = wid >> 2;
    int row0 = blockIdx.x * 128;
    int n0 = blockIdx.x * 8;

    float acc[2][8][4];
#pragma unroll
    for (int mt = 0; mt < 2; mt++)
#pragma unroll
        for (int nt = 0; nt < 8; nt++)
#pragma unroll
            for (int e = 0; e < 4; e++) acc[mt][nt][e] = 0.f;

    int arow = mw * 32 + (lane & 15);
    int akb = (lane >> 4) * 16;
    int bn = nw * 64 + (lane & 7) + ((lane >> 4) << 3);
    int bkb = ((lane >> 3) & 1) * 16;

    for (int ch = 0; ch < 5; ch++) {
        int k0 = ch * 64;
        for (int i = tid; i < 2048; i += 256) {
            int row = i >> 4, kq = i & 15;
            int kg = k0 + kq * 4;
            uint4 t = make_uint4(0u, 0u, 0u, 0u);
            if (kg < 300)
                t = *(const uint4*)&g_h2hl[(size_t)(row0 + row) * HH + kg];
            uint32_t h01 = __byte_perm(t.x, t.y, 0x5410);
            uint32_t h23 = __byte_perm(t.z, t.w, 0x5410);
            uint32_t l01 = __byte_perm(t.x, t.y, 0x7632);
            uint32_t l23 = __byte_perm(t.z, t.w, 0x7632);
            uint32_t o = sw128((uint32_t)(row * 128 + kq * 8));
            *(uint2*)(smem + SOFF_AH + o) = make_uint2(h01, h23);
            *(uint2*)(smem + SOFF_AL + o) = make_uint2(l01, l23);
        }
        for (int i = tid; i < 4096; i += 256) {
            int pl = i >= 2048;
            int j = i & 2047;
            int n = j >> 4, kq = j & 15;
            uint2 w = *(const uint2*)((pl ? Bl_g : Bh_g) + n * 320 + k0 + kq * 4);
            uint32_t o = sw128((uint32_t)(n * 128 + kq * 8));
            *(uint2*)(smem + (pl ? SOFF_BL : SOFF_BH) + o) = w;
        }
        __syncthreads();
#pragma unroll
        for (int s = 0; s < 4; s++) {
            uint32_t ah[2][4], al[2][4];
#pragma unroll
            for (int mt = 0; mt < 2; mt++) {
                uint32_t off = sw128((uint32_t)((arow + mt * 16) * 128 + akb + s * 32));
                ldsm4(sb + SOFF_AH + off, ah[mt]);
                ldsm4(sb + SOFF_AL + off, al[mt]);
            }
#pragma unroll
            for (int p = 0; p < 4; p++) {
                uint32_t bb[4];
                uint32_t off = sw128((uint32_t)((bn + p * 16) * 128 + bkb + s * 32));
                ldsm4(sb + SOFF_BH + off, bb);
#pragma unroll
                for (int mt = 0; mt < 2; mt++) {
                    mma16816(acc[mt][2 * p + 0], ah[mt], bb[0], bb[1]);
                    mma16816(acc[mt][2 * p + 1], ah[mt], bb[2], bb[3]);
                    mma16816(acc[mt][2 * p + 0], al[mt], bb[0], bb[1]);
                    mma16816(acc[mt][2 * p + 1], al[mt], bb[2], bb[3]);
                }
            }
#pragma unroll
            for (int p = 0; p < 4; p++) {
                uint32_t bb[4];
                uint32_t off = sw128((uint32_t)((bn + p * 16) * 128 + bkb + s * 32));
                ldsm4(sb + SOFF_BL + off, bb);
#pragma unroll
                for (int mt = 0; mt < 2; mt++) {
                    mma16816(acc[mt][2 * p + 0], ah[mt], bb[0], bb[1]);
                    mma16816(acc[mt][2 * p + 1], ah[mt], bb[2], bb[3]);
                }
            }
        }
        __syncthreads();
    }

    float* stagef = (float*)smem;        // [128][104] fp32 overlays tiles
#pragma unroll
    for (int mt = 0; mt < 2; mt++)
#pragma unroll
        for (int nt = 0; nt < 8; nt++) {
            int c = nw * 64 + nt * 8 + (lane & 3) * 2;
            int r0 = mw * 32 + mt * 16 + (lane >> 2);
#pragma unroll
            for (int e = 0; e < 4; e++) {
                int cc = c + (e & 1);
                int rr = (e < 2) ? r0 : r0 + 8;
                if (cc < 100) stagef[rr * 104 + cc] = acc[mt][nt][e];
            }
        }
    __syncthreads();
    for (int i = tid; i < 800; i += 256) {
        int n = i / 100, c = i - n * 100;
        float m = -CUDART_INF_F;
#pragma unroll
        for (int rr = 0; rr < 16; rr++)
            m = fmaxf(m, stagef[(n * 16 + rr) * 104 + c]);
        g_node[(n0 + n) * LL + c] = fmaxf(m + bias[c], 0.f);
    }
}

// ---------------------------------------------------------------------------
__global__ void pool_kernel() {
    __shared__ float ssum[8][100];
    __shared__ float smax[8][100];
    int g = blockIdx.x;
    int col = threadIdx.x % 100;
    int part = threadIdx.x / 100;
    float s = 0.f, m = -CUDART_INF_F;
    int base = g * 3200 + part * 400;
    for (int n = 0; n < 400; n++) {
        float v = g_node[(base + n) * LL + col];
        s += v;
        m = fmaxf(m, v);
    }
    ssum[part][col] = s;
    smax[part][col] = m;
    __syncthreads();
    if (part == 0) {
        for (int p = 1; p < 8; p++) {
            s += ssum[p][col];
            m = fmaxf(m, smax[p][col]);
        }
        g_pooled[g * 300 + col] = s;
        g_pooled[g * 300 + 100 + col] = s / 3200.0f;
        g_pooled[g * 300 + 200 + col] = m;
    }
}

__global__ void final_kernel(const float* __restrict__ W1, const float* __restrict__ b1,
                             const float* __restrict__ W2, const float* __restrict__ b2,
                             const float* __restrict__ W3, const float* __restrict__ b3,
                             float* __restrict__ out) {
    __shared__ float sp[GB * 300];
    __shared__ float t1[GB * 100];
    int j = threadIdx.x;
    for (int i = j; i < GB * 300; i += blockDim.x) sp[i] = g_pooled[i];
    __syncthreads();
    if (j < 100) {
        float acc[GB];
#pragma unroll
        for (int r = 0; r < GB; r++) acc[r] = b1[j];
        for (int k = 0; k < 300; k++) {
            float w = W1[k * 100 + j];
#pragma unroll
            for (int r = 0; r < GB; r++) acc[r] = fmaf(sp[r * 300 + k], w, acc[r]);
        }
#pragma unroll
        for (int r = 0; r < GB; r++) t1[r * 100 + j] = fmaxf(acc[r], 0.f);
    }
    __syncthreads();
    float acc2[GB];
    if (j < 100) {
#pragma unroll
        for (int r = 0; r < GB; r++) acc2[r] = b2[j];
        for (int k = 0; k < 100; k++) {
            float w = W2[k * 100 + j];
#pragma unroll
            for (int r = 0; r < GB; r++) acc2[r] = fmaf(t1[r * 100 + k], w, acc2[r]);
        }
    }
    __syncthreads();
    if (j < 100) {
#pragma unroll
        for (int r = 0; r < GB; r++) sp[r * 100 + j] = fmaxf(acc2[r], 0.f);
    }
    __syncthreads();
    if (j < GB) {
        float s = b3[0];
        for (int k = 0; k < 100; k++) s = fmaf(sp[j * 100 + k], W3[k], s);
        out[j] = s;
    }
}

// ---------------------------------------------------------------------------
extern "C" void kernel_launch(void* const* d_in, const int* in_sizes, int n_in,
                              void* d_out, int out_size) {
    const float* x     = (const float*)d_in[0];
    const int*   eidx  = (const int*)d_in[1];
    const float* l0_W1 = (const float*)d_in[3];
    const float* l0_b1 = (const float*)d_in[4];
    const float* l0_W2 = (const float*)d_in[5];
    const float* l0_b2 = (const float*)d_in[6];
    const float* l0_W3 = (const float*)d_in[7];
    const float* l0_b3 = (const float*)d_in[8];
    const float* l1_W1 = (const float*)d_in[9];
    const float* l1_b1 = (const float*)d_in[10];
    const float* l1_W2 = (const float*)d_in[11];
    const float* l1_b2 = (const float*)d_in[12];
    const float* l1_W3 = (const float*)d_in[13];
    const float* l1_b3 = (const float*)d_in[14];
    const float* lin_W1 = (const float*)d_in[15];
    const float* lin_b1 = (const float*)d_in[16];
    const float* lin_W2 = (const float*)d_in[17];
    const float* lin_b2 = (const float*)d_in[18];
    const float* lin_W3 = (const float*)d_in[19];
    const float* lin_b3 = (const float*)d_in[20];

    const int* src = eidx;

    cudaFuncSetAttribute(gemm_mid_mma, cudaFuncAttributeMaxDynamicSharedMemorySize, SMEM_MID);
    cudaFuncSetAttribute(gemm_out_mma, cudaFuncAttributeMaxDynamicSharedMemorySize, SMEMTC);

    __nv_bfloat16 *w2h0, *w2l0, *w2h1, *w2l1, *w3h0, *w3l0, *w3h1, *w3l1;
    cudaGetSymbolAddress((void**)&w2h0, g_W2h);
    cudaGetSymbolAddress((void**)&w2l0, g_W2l);
    cudaGetSymbolAddress((void**)&w3h0, g_W3h);
    cudaGetSymbolAddress((void**)&w3l0, g_W3l);
    w2h1 = w2h0 + 2 * 160 * 320; w2l1 = w2l0 + 2 * 160 * 320;
    w3h1 = w3h0 + 128 * 320;     w3l1 = w3l0 + 128 * 320;

    // weight prep (tiny): W2 -> 2 slabs x 160 rows (150 valid), W3 -> 128 rows
    split_w<<<2 * 160, 320>>>(l0_W2, w2h0, w2l0, 300, 300, 160, 150);
    split_w<<<128, 320>>>(l0_W3, w3h0, w3l0, 300, 100, 128, 100);
    split_w<<<2 * 160, 320>>>(l1_W2, w2h1, w2l1, 300, 300, 160, 150);
    split_w<<<128, 320>>>(l1_W3, w3h1, w3l1, 300, 100, 128, 100);

    // ---- layer 0 ----
    front_kernel<<<NN / 16, 300>>>(x, FF, l0_W1, l0_b1, 0);
    gemm_mid_mma<<<dim3(2, EE / 128), 256, SMEM_MID>>>(src, w2h0, w2l0, l0_b2);
    gemm_out_mma<<<EE / 128, 256, SMEMTC>>>(w3h0, w3l0, l0_b3);
    // ---- layer 1 ----
    front_kernel<<<NN / 16, 300>>>(nullptr, LL, l1_W1, l1_b1, 1);
    gemm_mid_mma<<<dim3(2, EE / 128), 256, SMEM_MID>>>(src, w2h1, w2l1, l1_b2);
    gemm_out_mma<<<EE / 128, 256, SMEMTC>>>(w3h1, w3l1, l1_b3);
    // ---- pooling + head ----
    pool_kernel<<<GB, 800>>>();
    final_kernel<<<1, 128>>>(lin_W1, lin_b1, lin_W2, lin_b2, lin_W3, lin_b3,
                             (float*)d_out);
}

// round 14
// speedup vs baseline: 1.4202x; 1.4202x over previous
#include <cuda_runtime.h>
#include <cuda_bf16.h>
#include <math_constants.h>
#include <cstdint>

#define NN 25600
#define EE 409600
#define GB 8
#define FF 7
#define HH 300
#define LL 100

// ---- GEMM smem layout (both kernels): A single-buffer, B double-buffer ----
#define T_AH   0        // A hi  [128 rows][64 k] bf16, 128B rows, SW128
#define T_AL   16384    // A lo
#define T_BH0  32768    // B hi buf0 [128 n-rows][64 k]
#define T_BL0  49152    // B lo buf0
#define T_BH1  65536    // B hi buf1
#define T_BL1  81920    // B lo buf1
#define SMEM_GEMM 98304

// ---------------- scratch (static device globals; no runtime allocation) ----
__device__ float    g_P[NN * HH];
__device__ float    g_Q[NN * HH];
__device__ unsigned short g_Ah[(size_t)EE * 320];   // edge-feature bf16 hi plane
__device__ unsigned short g_Al[(size_t)EE * 320];   // edge-feature bf16 lo plane
__device__ unsigned short g_h2h[(size_t)EE * 320];  // h2 bf16 hi plane (padded)
__device__ unsigned short g_h2l[(size_t)EE * 320];  // h2 bf16 lo plane
__device__ float    g_node[NN * LL];
__device__ float    g_pooled[GB * 3 * LL];
// pre-split / transposed / padded weights: B[n][k] = W[k][n], rows padded to 320
__device__ __nv_bfloat16 g_W2h[2][3 * 128 * 320];
__device__ __nv_bfloat16 g_W2l[2][3 * 128 * 320];
__device__ __nv_bfloat16 g_W3h[2][128 * 320];
__device__ __nv_bfloat16 g_W3l[2][128 * 320];

// ---------------- PTX helpers (baseline compute_103 instructions only) ------
__device__ __forceinline__ uint32_t smem_u32(const void* p) {
    uint32_t a;
    asm("{ .reg .u64 t; cvta.to.shared.u64 t, %1; cvt.u32.u64 %0, t; }"
        : "=r"(a) : "l"(p));
    return a;
}
__device__ __forceinline__ uint32_t sw128(uint32_t o) {
    return o ^ ((o >> 3) & 0x70);
}
__device__ __forceinline__ uint32_t bf2pack(float hi, float lo) {
    uint32_t r;
    asm("cvt.rn.bf16x2.f32 %0, %1, %2;" : "=r"(r) : "f"(hi), "f"(lo));
    return r;
}
__device__ __forceinline__ void ldsm4(uint32_t addr, uint32_t* r) {
    asm volatile("ldmatrix.sync.aligned.m8n8.x4.shared.b16 {%0,%1,%2,%3}, [%4];"
                 : "=r"(r[0]), "=r"(r[1]), "=r"(r[2]), "=r"(r[3]) : "r"(addr));
}
__device__ __forceinline__ void mma16816(float* d, const uint32_t* a,
                                         uint32_t b0, uint32_t b1) {
    asm volatile(
        "mma.sync.aligned.m16n8k16.row.col.f32.bf16.bf16.f32 "
        "{%0,%1,%2,%3}, {%4,%5,%6,%7}, {%8,%9}, {%0,%1,%2,%3};"
        : "+f"(d[0]), "+f"(d[1]), "+f"(d[2]), "+f"(d[3])
        : "r"(a[0]), "r"(a[1]), "r"(a[2]), "r"(a[3]), "r"(b0), "r"(b1));
}
__device__ __forceinline__ void cpa16(uint32_t dst, const void* src) {
    asm volatile("cp.async.cg.shared.global [%0], [%1], 16;" :: "r"(dst), "l"(src));
}
__device__ __forceinline__ void cpa_commit() {
    asm volatile("cp.async.commit_group;");
}
__device__ __forceinline__ void cpa_wait1() {
    asm volatile("cp.async.wait_group 1;");
}
__device__ __forceinline__ void cpa_wait0() {
    asm volatile("cp.async.wait_group 0;");
}

// ---------------------------------------------------------------------------
// split weights into bf16 hi/lo planes, transposed to B[n][k], padded to 320.
// grid = n_slabs * rows_per_slab; slab s covers cols [s*valid, s*valid+valid).
__global__ void split_w(const float* __restrict__ W,
                        __nv_bfloat16* __restrict__ oh,
                        __nv_bfloat16* __restrict__ ol,
                        int K, int Ncols, int rows_per_slab, int valid) {
    int b = blockIdx.x;
    int slab = b / rows_per_slab;
    int n_local = b - slab * rows_per_slab;
    int k = threadIdx.x;
    int n = slab * valid + n_local;
    float v = 0.f;
    if (n_local < valid && k < K && n < Ncols) v = W[k * Ncols + n];
    __nv_bfloat16 h = __float2bfloat16(v);
    __nv_bfloat16 l = __float2bfloat16(v - __bfloat162float(h));
    oh[b * 320 + k] = h;
    ol[b * 320 + k] = l;
}

// ---------------------------------------------------------------------------
// front: per-node first MLP layer, exploiting linearity of concat([x_i, x_j-x_i]).
__global__ void front_kernel(const float* __restrict__ xin, int K,
                             const float* __restrict__ W,
                             const float* __restrict__ b,
                             int from_node) {
    __shared__ float xs[16 * 100];
    const float* __restrict__ x = from_node ? g_node : xin;
    int n0 = blockIdx.x * 16;
    int j = threadIdx.x;
    for (int i = threadIdx.x; i < 16 * K; i += 300)
        xs[i] = x[n0 * K + i];
    __syncthreads();

    float accP[16], accQ[16];
    float bj = b[j];
#pragma unroll
    for (int r = 0; r < 16; r++) { accP[r] = bj; accQ[r] = 0.f; }
    for (int k = 0; k < K; k++) {
        float wa = W[k * HH + j];
        float wb = W[(K + k) * HH + j];
        float d = wa - wb;
#pragma unroll
        for (int r = 0; r < 16; r++) {
            float xv = xs[r * K + k];
            accP[r] = fmaf(xv, d, accP[r]);
            accQ[r] = fmaf(xv, wb, accQ[r]);
        }
    }
#pragma unroll
    for (int r = 0; r < 16; r++) {
        g_P[(n0 + r) * HH + j] = accP[r];
        g_Q[(n0 + r) * HH + j] = accQ[r];
    }
}

// ---------------------------------------------------------------------------
// edge_feat: materialize per-edge bf16 hi/lo planes ONCE:
//   A[e, k] = relu(P[dst(e), k] + Q[src(e), k]), split into hi/lo, pad to 320.
// CTA = 128 edges; 256 threads; element granularity = float4 (k multiple of 4).
__global__ __launch_bounds__(256) void edge_feat(const int* __restrict__ src) {
    __shared__ int s_src[128];
    int tid = threadIdx.x;
    int row0 = blockIdx.x * 128;
    int n0 = blockIdx.x * 8;
    if (tid < 128) s_src[tid] = src[row0 + tid];
    __syncthreads();

    for (int i = tid; i < 128 * 80; i += 256) {
        int row = i / 80, g = i - row * 80;  // g = float4 group, k = 4g
        int k = g * 4;
        uint32_t h01 = 0, h23 = 0, q01 = 0, q23 = 0;
        if (g < 75) {                        // 300/4 = 75 exactly
            float4 p = *(const float4*)&g_P[(n0 + (row >> 4)) * HH + k];
            float4 q = *(const float4*)&g_Q[s_src[row] * HH + k];
            float4 v;
            v.x = fmaxf(p.x + q.x, 0.f);
            v.y = fmaxf(p.y + q.y, 0.f);
            v.z = fmaxf(p.z + q.z, 0.f);
            v.w = fmaxf(p.w + q.w, 0.f);
            h01 = bf2pack(v.y, v.x);
            h23 = bf2pack(v.w, v.z);
            float l0 = v.x - __uint_as_float(h01 << 16);
            float l1 = v.y - __uint_as_float(h01 & 0xFFFF0000u);
            float l2 = v.z - __uint_as_float(h23 << 16);
            float l3 = v.w - __uint_as_float(h23 & 0xFFFF0000u);
            q01 = bf2pack(l1, l0);
            q23 = bf2pack(l3, l2);
        }
        size_t o = (size_t)(row0 + row) * 320 + k;
        *(uint2*)&g_Ah[o] = make_uint2(h01, h23);
        *(uint2*)&g_Al[o] = make_uint2(q01, q23);
    }
}

// ---------------------------------------------------------------------------
// Shared fill helpers: pure cp.async copies of one 64-k chunk of a bf16 plane
// pair (128 rows x 64 k = 128 B/row) into SW128-swizzled smem tiles.
__device__ __forceinline__ void cpa_tile(uint32_t sb, uint32_t off_h, uint32_t off_l,
                                         const unsigned short* ph,
                                         const unsigned short* pl,
                                         size_t row_base, int k0, int tid) {
#pragma unroll
    for (int i = tid; i < 2048; i += 256) {
        int plane = i >= 1024;
        int j = i & 1023;
        int row = j >> 3, u = j & 7;
        const unsigned short* s =
            (plane ? pl : ph) + row_base + (size_t)row * 320 + k0 + u * 8;
        uint32_t d = sb + (plane ? off_l : off_h) + sw128((uint32_t)(row * 128 + u * 16));
        cpa16(d, s);
    }
}

// Core warp-MMA over one staged 64-k chunk (R11-validated mapping).
__device__ __forceinline__ void mma_chunk(uint32_t sb, uint32_t bh, uint32_t bl,
                                          int arow, int akb, int bn, int bkb,
                                          float acc[2][8][4]) {
#pragma unroll
    for (int s = 0; s < 4; s++) {
        uint32_t ah[2][4], al[2][4];
#pragma unroll
        for (int mt = 0; mt < 2; mt++) {
            uint32_t off = sw128((uint32_t)((arow + mt * 16) * 128 + akb + s * 32));
            ldsm4(sb + T_AH + off, ah[mt]);
            ldsm4(sb + T_AL + off, al[mt]);
        }
#pragma unroll
        for (int p = 0; p < 4; p++) {
            uint32_t bb[4];
            uint32_t off = sw128((uint32_t)((bn + p * 16) * 128 + bkb + s * 32));
            ldsm4(bh + off, bb);
#pragma unroll
            for (int mt = 0; mt < 2; mt++) {
                mma16816(acc[mt][2 * p + 0], ah[mt], bb[0], bb[1]);
                mma16816(acc[mt][2 * p + 1], ah[mt], bb[2], bb[3]);
                mma16816(acc[mt][2 * p + 0], al[mt], bb[0], bb[1]);
                mma16816(acc[mt][2 * p + 1], al[mt], bb[2], bb[3]);
            }
        }
#pragma unroll
        for (int p = 0; p < 4; p++) {
            uint32_t bb[4];
            uint32_t off = sw128((uint32_t)((bn + p * 16) * 128 + bkb + s * 32));
            ldsm4(bl + off, bb);
#pragma unroll
            for (int mt = 0; mt < 2; mt++) {
                mma16816(acc[mt][2 * p + 0], ah[mt], bb[0], bb[1]);
                mma16816(acc[mt][2 * p + 1], ah[mt], bb[2], bb[3]);
            }
        }
    }
}

// ---------------------------------------------------------------------------
// gemm_mid_mma: h2[128 edges, 100-col slab] = relu(A @ W2 + b2).
// A from pre-built g_Ah/g_Al planes (cp.async), B double-buffered cp.async.
__global__ __launch_bounds__(256, 2)
void gemm_mid_mma(const __nv_bfloat16* __restrict__ Bh_g,
                  const __nv_bfloat16* __restrict__ Bl_g,
                  const float* __restrict__ bias) {
    extern __shared__ char smem[];
    uint32_t sb = smem_u32(smem);
    int tid = threadIdx.x, wid = tid >> 5, lane = tid & 31;
    int mw = wid & 3, nw = wid >> 2;
    int slab = blockIdx.x;
    int row0 = blockIdx.y * 128;
    size_t arow_base = (size_t)row0 * 320;

    const unsigned short* bhp = (const unsigned short*)(Bh_g + slab * (128 * 320));
    const unsigned short* blp = (const unsigned short*)(Bl_g + slab * (128 * 320));

    float acc[2][8][4];
#pragma unroll
    for (int mt = 0; mt < 2; mt++)
#pragma unroll
        for (int nt = 0; nt < 8; nt++)
#pragma unroll
            for (int e = 0; e < 4; e++) acc[mt][nt][e] = 0.f;

    int arow = mw * 32 + (lane & 15);
    int akb = (lane >> 4) * 16;
    int bn = nw * 64 + (lane & 7) + ((lane >> 4) << 3);
    int bkb = ((lane >> 3) & 1) * 16;

    // prologue: B(0) into buf0
    cpa_tile(sb, T_BH0, T_BL0, bhp, blp, 0, 0, tid);
    cpa_commit();

    for (int ch = 0; ch < 5; ch++) {
        int k0 = ch * 64;
        // A(ch) (own commit group)
        cpa_tile(sb, T_AH, T_AL, g_Ah, g_Al, arow_base, k0, tid);
        cpa_commit();
        if (ch < 4) {
            int nb = (ch + 1) & 1;
            cpa_tile(sb, nb ? T_BH1 : T_BH0, nb ? T_BL1 : T_BL0,
                     bhp, blp, 0, k0 + 64, tid);
            cpa_commit();
            cpa_wait1();          // A(ch), B(ch) done; B(ch+1) in flight
        } else {
            cpa_wait0();
        }
        __syncthreads();
        int cb = ch & 1;
        mma_chunk(sb, sb + (cb ? T_BH1 : T_BH0), sb + (cb ? T_BL1 : T_BL0),
                  arow, akb, bn, bkb, acc);
        __syncthreads();
    }

    // epilogue: bias + relu + split -> h2 planes (stride 320; slab2 zeros pad)
    uint32_t* stage = (uint32_t*)smem;   // [128][104] packed (hi | lo<<16)
#pragma unroll
    for (int mt = 0; mt < 2; mt++)
#pragma unroll
        for (int nt = 0; nt < 8; nt++) {
            int c = nw * 64 + nt * 8 + (lane & 3) * 2;
            int r0 = mw * 32 + mt * 16 + (lane >> 2);
#pragma unroll
            for (int e = 0; e < 4; e++) {
                int cc = c + (e & 1);
                int rr = (e < 2) ? r0 : r0 + 8;
                if (cc < 100) {
                    float v = fmaxf(acc[mt][nt][e] + bias[slab * 100 + cc], 0.f);
                    __nv_bfloat16 hh = __float2bfloat16(v);
                    __nv_bfloat16 ll = __float2bfloat16(v - __bfloat162float(hh));
                    stage[rr * 104 + cc] =
                        ((uint32_t)__bfloat16_as_ushort(ll) << 16) |
                        __bfloat16_as_ushort(hh);
                }
            }
        }
    __syncthreads();
    for (int i = tid; i < 12800; i += 256) {
        int row = i / 100, c = i - row * 100;
        uint32_t v = stage[row * 104 + c];
        size_t o = (size_t)(row0 + row) * 320 + slab * 100 + c;
        g_h2h[o] = (unsigned short)(v & 0xFFFFu);
        g_h2l[o] = (unsigned short)(v >> 16);
    }
    if (slab == 2) {  // zero the k-pad [300,320) once per row block
        for (int i = tid; i < 128 * 20; i += 256) {
            int row = i / 20, c = i - row * 20;
            size_t o = (size_t)(row0 + row) * 320 + 300 + c;
            g_h2h[o] = 0;
            g_h2l[o] = 0;
        }
    }
}

// ---------------------------------------------------------------------------
// gemm_out_mma: h3 = h2 @ W3 (planes via cp.async), fused max over 16-edge
// groups, +b3, relu -> g_node.
__global__ __launch_bounds__(256, 2)
void gemm_out_mma(const __nv_bfloat16* __restrict__ Bh_g,
                  const __nv_bfloat16* __restrict__ Bl_g,
                  const float* __restrict__ bias) {
    extern __shared__ char smem[];
    uint32_t sb = smem_u32(smem);
    int tid = threadIdx.x, wid = tid >> 5, lane = tid & 31;
    int mw = wid & 3, nw = wid >> 2;
    int row0 = blockIdx.x * 128;
    int n0 = blockIdx.x * 8;
    size_t arow_base = (size_t)row0 * 320;

    const unsigned short* bhp = (const unsigned short*)Bh_g;
    const unsigned short* blp = (const unsigned short*)Bl_g;

    float acc[2][8][4];
#pragma unroll
    for (int mt = 0; mt < 2; mt++)
#pragma unroll
        for (int nt = 0; nt < 8; nt++)
#pragma unroll
            for (int e = 0; e < 4; e++) acc[mt][nt][e] = 0.f;

    int arow = mw * 32 + (lane & 15);
    int akb = (lane >> 4) * 16;
    int bn = nw * 64 + (lane & 7) + ((lane >> 4) << 3);
    int bkb = ((lane >> 3) & 1) * 16;

    cpa_tile(sb, T_BH0, T_BL0, bhp, blp, 0, 0, tid);
    cpa_commit();

    for (int ch = 0; ch < 5; ch++) {
        int k0 = ch * 64;
        cpa_tile(sb, T_AH, T_AL, g_h2h, g_h2l, arow_base, k0, tid);
        cpa_commit();
        if (ch < 4) {
            int nb = (ch + 1) & 1;
            cpa_tile(sb, nb ? T_BH1 : T_BH0, nb ? T_BL1 : T_BL0,
                     bhp, blp, 0, k0 + 64, tid);
            cpa_commit();
            cpa_wait1();
        } else {
            cpa_wait0();
        }
        __syncthreads();
        int cb = ch & 1;
        mma_chunk(sb, sb + (cb ? T_BH1 : T_BH0), sb + (cb ? T_BL1 : T_BL0),
                  arow, akb, bn, bkb, acc);
        __syncthreads();
    }

    float* stagef = (float*)smem;        // [128][104]
#pragma unroll
    for (int mt = 0; mt < 2; mt++)
#pragma unroll
        for (int nt = 0; nt < 8; nt++) {
            int c = nw * 64 + nt * 8 + (lane & 3) * 2;
            int r0 = mw * 32 + mt * 16 + (lane >> 2);
#pragma unroll
            for (int e = 0; e < 4; e++) {
                int cc = c + (e & 1);
                int rr = (e < 2) ? r0 : r0 + 8;
                if (cc < 100) stagef[rr * 104 + cc] = acc[mt][nt][e];
            }
        }
    __syncthreads();
    for (int i = tid; i < 800; i += 256) {
        int n = i / 100, c = i - n * 100;
        float m = -CUDART_INF_F;
#pragma unroll
        for (int rr = 0; rr < 16; rr++)
            m = fmaxf(m, stagef[(n * 16 + rr) * 104 + c]);
        g_node[(n0 + n) * LL + c] = fmaxf(m + bias[c], 0.f);
    }
}

// ---------------------------------------------------------------------------
__global__ void pool_kernel() {
    __shared__ float ssum[8][100];
    __shared__ float smax[8][100];
    int g = blockIdx.x;
    int col = threadIdx.x % 100;
    int part = threadIdx.x / 100;
    float s = 0.f, m = -CUDART_INF_F;
    int base = g * 3200 + part * 400;
    for (int n = 0; n < 400; n++) {
        float v = g_node[(base + n) * LL + col];
        s += v;
        m = fmaxf(m, v);
    }
    ssum[part][col] = s;
    smax[part][col] = m;
    __syncthreads();
    if (part == 0) {
        for (int p = 1; p < 8; p++) {
            s += ssum[p][col];
            m = fmaxf(m, smax[p][col]);
        }
        g_pooled[g * 300 + col] = s;
        g_pooled[g * 300 + 100 + col] = s / 3200.0f;
        g_pooled[g * 300 + 200 + col] = m;
    }
}

__global__ void final_kernel(const float* __restrict__ W1, const float* __restrict__ b1,
                             const float* __restrict__ W2, const float* __restrict__ b2,
                             const float* __restrict__ W3, const float* __restrict__ b3,
                             float* __restrict__ out) {
    __shared__ float sp[GB * 300];
    __shared__ float t1[GB * 100];
    int j = threadIdx.x;
    for (int i = j; i < GB * 300; i += blockDim.x) sp[i] = g_pooled[i];
    __syncthreads();
    if (j < 100) {
        float acc[GB];
#pragma unroll
        for (int r = 0; r < GB; r++) acc[r] = b1[j];
        for (int k = 0; k < 300; k++) {
            float w = W1[k * 100 + j];
#pragma unroll
            for (int r = 0; r < GB; r++) acc[r] = fmaf(sp[r * 300 + k], w, acc[r]);
        }
#pragma unroll
        for (int r = 0; r < GB; r++) t1[r * 100 + j] = fmaxf(acc[r], 0.f);
    }
    __syncthreads();
    float acc2[GB];
    if (j < 100) {
#pragma unroll
        for (int r = 0; r < GB; r++) acc2[r] = b2[j];
        for (int k = 0; k < 100; k++) {
            float w = W2[k * 100 + j];
#pragma unroll
            for (int r = 0; r < GB; r++) acc2[r] = fmaf(t1[r * 100 + k], w, acc2[r]);
        }
    }
    __syncthreads();
    if (j < 100) {
#pragma unroll
        for (int r = 0; r < GB; r++) sp[r * 100 + j] = fmaxf(acc2[r], 0.f);
    }
    __syncthreads();
    if (j < GB) {
        float s = b3[0];
        for (int k = 0; k < 100; k++) s = fmaf(sp[j * 100 + k], W3[k], s);
        out[j] = s;
    }
}

// ---------------------------------------------------------------------------
extern "C" void kernel_launch(void* const* d_in, const int* in_sizes, int n_in,
                              void* d_out, int out_size) {
    const float* x     = (const float*)d_in[0];
    const int*   eidx  = (const int*)d_in[1];
    const float* l0_W1 = (const float*)d_in[3];
    const float* l0_b1 = (const float*)d_in[4];
    const float* l0_W2 = (const float*)d_in[5];
    const float* l0_b2 = (const float*)d_in[6];
    const float* l0_W3 = (const float*)d_in[7];
    const float* l0_b3 = (const float*)d_in[8];
    const float* l1_W1 = (const float*)d_in[9];
    const float* l1_b1 = (const float*)d_in[10];
    const float* l1_W2 = (const float*)d_in[11];
    const float* l1_b2 = (const float*)d_in[12];
    const float* l1_W3 = (const float*)d_in[13];
    const float* l1_b3 = (const float*)d_in[14];
    const float* lin_W1 = (const float*)d_in[15];
    const float* lin_b1 = (const float*)d_in[16];
    const float* lin_W2 = (const float*)d_in[17];
    const float* lin_b2 = (const float*)d_in[18];
    const float* lin_W3 = (const float*)d_in[19];
    const float* lin_b3 = (const float*)d_in[20];

    const int* src = eidx;

    cudaFuncSetAttribute(gemm_mid_mma, cudaFuncAttributeMaxDynamicSharedMemorySize, SMEM_GEMM);
    cudaFuncSetAttribute(gemm_out_mma, cudaFuncAttributeMaxDynamicSharedMemorySize, SMEM_GEMM);

    __nv_bfloat16 *w2h0, *w2l0, *w2h1, *w2l1, *w3h0, *w3l0, *w3h1, *w3l1;
    cudaGetSymbolAddress((void**)&w2h0, g_W2h);
    cudaGetSymbolAddress((void**)&w2l0, g_W2l);
    cudaGetSymbolAddress((void**)&w3h0, g_W3h);
    cudaGetSymbolAddress((void**)&w3l0, g_W3l);
    w2h1 = w2h0 + 3 * 128 * 320; w2l1 = w2l0 + 3 * 128 * 320;
    w3h1 = w3h0 + 128 * 320;     w3l1 = w3l0 + 128 * 320;

    // weight prep (tiny): W2 -> 3 slabs x 128 rows (100 valid), W3 -> 128 rows
    split_w<<<3 * 128, 320>>>(l0_W2, w2h0, w2l0, 300, 300, 128, 100);
    split_w<<<128, 320>>>(l0_W3, w3h0, w3l0, 300, 100, 128, 100);
    split_w<<<3 * 128, 320>>>(l1_W2, w2h1, w2l1, 300, 300, 128, 100);
    split_w<<<128, 320>>>(l1_W3, w3h1, w3l1, 300, 100, 128, 100);

    // ---- layer 0 ----
    front_kernel<<<NN / 16, 300>>>(x, FF, l0_W1, l0_b1, 0);
    edge_feat<<<EE / 128, 256>>>(src);
    gemm_mid_mma<<<dim3(3, EE / 128), 256, SMEM_GEMM>>>(w2h0, w2l0, l0_b2);
    gemm_out_mma<<<EE / 128, 256, SMEM_GEMM>>>(w3h0, w3l0, l0_b3);
    // ---- layer 1 ----
    front_kernel<<<NN / 16, 300>>>(nullptr, LL, l1_W1, l1_b1, 1);
    edge_feat<<<EE / 128, 256>>>(src);
    gemm_mid_mma<<<dim3(3, EE / 128), 256, SMEM_GEMM>>>(w2h1, w2l1, l1_b2);
    gemm_out_mma<<<EE / 128, 256, SMEM_GEMM>>>(w3h1, w3l1, l1_b3);
    // ---- pooling + head ----
    pool_kernel<<<GB, 800>>>();
    final_kernel<<<1, 128>>>(lin_W1, lin_b1, lin_W2, lin_b2, lin_W3, lin_b3,
                             (float*)d_out);
}